// round 4
// baseline (speedup 1.0000x reference)
#include <cuda_runtime.h>
#include <math.h>

#define G3 32768
#define NVIEW 8
#define NF 32
#define FULLMASK 0xFFFFFFFFu

__device__ __forceinline__ float elu_f(float x) { return x > 0.f ? x : expm1f(x); }
__device__ __forceinline__ float sigm_f(float x) { return 1.f / (1.f + expf(-x)); }

__global__ __launch_bounds__(256)
void ibr_agg_kernel(
    const float* __restrict__ features,   // (B,N,32,G3)
    const float* __restrict__ mask,       // (B,N,1,G3)
    const float* __restrict__ depth,      // (B,N,1,G3)
    const float* __restrict__ vdir,       // (B,N,3,G3)
    const float* __restrict__ g_rw1, const float* __restrict__ g_rb1,   // (16,4),(16)
    const float* __restrict__ g_rw2, const float* __restrict__ g_rb2,   // (32,16),(32)
    const float* __restrict__ g_bw1, const float* __restrict__ g_bb1,   // (64,96),(64)
    const float* __restrict__ g_bw2, const float* __restrict__ g_bb2,   // (32,64),(32)
    const float* __restrict__ g_vw1, const float* __restrict__ g_vb1,   // (32,32),(32)
    const float* __restrict__ g_vw2, const float* __restrict__ g_vb2,   // (33,32),(33)
    const float* __restrict__ g_v2w1, const float* __restrict__ g_v2b1, // (32,32),(32)
    const float* __restrict__ g_v2w2, const float* __restrict__ g_v2b2, // (1,32),(1)
    const float* __restrict__ g_sw,  const float* __restrict__ g_sb,    // (32,65),(32)
    float* __restrict__ out)              // (B,32,G3)
{
    // Transposed (C-major) weight staging: lane reads w[c*O + lane] -> conflict-free.
    __shared__ float s_rw1T[4 * 16];
    __shared__ float s_rb1[16];
    __shared__ float s_rw2T[16 * 32];
    __shared__ float s_rb2[32];
    __shared__ float s_bw1T[96 * 64];
    __shared__ float s_bb1[64];
    __shared__ float s_bw2T[64 * 32];
    __shared__ float s_bb2[32];
    __shared__ float s_vw1T[32 * 32];
    __shared__ float s_vb1[32];
    __shared__ float s_vw2T[32 * 33];
    __shared__ float s_vb2[33];
    __shared__ float s_v2w1T[32 * 32];
    __shared__ float s_v2b1[32];
    __shared__ float s_v2w2[32];
    __shared__ float s_sb[32];

    const int tid = threadIdx.x;

    // ---- stage weights (transposed) ----
    {
        // rde_w1 (16,4)
        for (int i = tid; i < 16 * 4; i += 256) { int o = i / 4, c = i % 4; s_rw1T[c * 16 + o] = g_rw1[i]; }
        for (int i = tid; i < 16; i += 256) s_rb1[i] = g_rb1[i];
        // rde_w2 (32,16)
        for (int i = tid; i < 32 * 16; i += 256) { int o = i / 16, c = i % 16; s_rw2T[c * 32 + o] = g_rw2[i]; }
        for (int i = tid; i < 32; i += 256) s_rb2[i] = g_rb2[i];
        // base_w1 (64,96)
        for (int i = tid; i < 64 * 96; i += 256) { int o = i / 96, c = i % 96; s_bw1T[c * 64 + o] = g_bw1[i]; }
        for (int i = tid; i < 64; i += 256) s_bb1[i] = g_bb1[i];
        // base_w2 (32,64)
        for (int i = tid; i < 32 * 64; i += 256) { int o = i / 64, c = i % 64; s_bw2T[c * 32 + o] = g_bw2[i]; }
        for (int i = tid; i < 32; i += 256) s_bb2[i] = g_bb2[i];
        // vis_w1 (32,32)
        for (int i = tid; i < 32 * 32; i += 256) { int o = i / 32, c = i % 32; s_vw1T[c * 32 + o] = g_vw1[i]; }
        for (int i = tid; i < 32; i += 256) s_vb1[i] = g_vb1[i];
        // vis_w2 (33,32)
        for (int i = tid; i < 33 * 32; i += 256) { int o = i / 32, c = i % 32; s_vw2T[c * 33 + o] = g_vw2[i]; }
        for (int i = tid; i < 33; i += 256) s_vb2[i] = g_vb2[i];
        // vis2_w1 (32,32)
        for (int i = tid; i < 32 * 32; i += 256) { int o = i / 32, c = i % 32; s_v2w1T[c * 32 + o] = g_v2w1[i]; }
        for (int i = tid; i < 32; i += 256) s_v2b1[i] = g_v2b1[i];
        // vis2_w2 (1,32) — used as a uniform row
        for (int i = tid; i < 32; i += 256) s_v2w2[i] = g_v2w2[i];
        for (int i = tid; i < 32; i += 256) s_sb[i] = g_sb[i];
    }
    __syncthreads();

    const int lane = tid & 31;
    const int l16  = lane & 15;
    const float v2b2 = __ldg(&g_v2w2[0] - (g_v2w2 - g_v2w2)) * 0.f + __ldg(g_v2b2); // scalar bias
    const float EPS = 1e-8f;

    // 8 warps/block, 8 voxels/warp -> 64 voxels/block
    const int warpGlobal = blockIdx.x * 8 + (tid >> 5);
    const int voxBase = warpGlobal * 8;

    for (int vi = 0; vi < 8; ++vi) {
        const int gv = voxBase + vi;          // [0, 65536)
        const int b  = gv >> 15;
        const int v  = gv & (G3 - 1);

        // ---------------- Stage 1: rde + feats, mask ----------------
        float fr[NVIEW];   // feats per view, lane = channel
        float m[NVIEW];    // mask per view (warp-uniform)

        #pragma unroll
        for (int n = 0; n < NVIEW; ++n) {
            const int bn = b * NVIEW + n;
            const float in0 = __ldg(&vdir[(bn * 3 + 0) * G3 + v]);
            const float in1 = __ldg(&vdir[(bn * 3 + 1) * G3 + v]);
            const float in2 = __ldg(&vdir[(bn * 3 + 2) * G3 + v]);
            const float in3 = __ldg(&depth[bn * G3 + v]);

            float h = s_rb1[l16];
            h += s_rw1T[0 * 16 + l16] * in0;
            h += s_rw1T[1 * 16 + l16] * in1;
            h += s_rw1T[2 * 16 + l16] * in2;
            h += s_rw1T[3 * 16 + l16] * in3;
            h = elu_f(h);

            float acc = s_rb2[lane];
            #pragma unroll
            for (int k = 0; k < 16; ++k)
                acc += s_rw2T[k * 32 + lane] * __shfl_sync(FULLMASK, h, k);
            const float rde = elu_f(acc);

            fr[n] = __ldg(&features[(bn * NF + lane) * G3 + v]) + rde;
            m[n]  = __ldg(&mask[bn * G3 + v]);
        }

        // ---------------- weights + mean/var over views ----------------
        float msum = 0.f;
        #pragma unroll
        for (int n = 0; n < NVIEW; ++n) msum += m[n];
        const float minv = 1.f / (msum + EPS);
        float w[NVIEW];
        #pragma unroll
        for (int n = 0; n < NVIEW; ++n) w[n] = m[n] * minv;

        float mean = 0.f;
        #pragma unroll
        for (int n = 0; n < NVIEW; ++n) mean += w[n] * fr[n];
        float var = 0.f;
        #pragma unroll
        for (int n = 0; n < NVIEW; ++n) { float d = fr[n] - mean; var += w[n] * d * d; }

        // ---------------- base MLP: [mean,var,feats] (96) -> 64 -> 32 ----------------
        float a0[NVIEW], a1[NVIEW];
        #pragma unroll
        for (int n = 0; n < NVIEW; ++n) { a0[n] = s_bb1[lane]; a1[n] = s_bb1[32 + lane]; }

        #pragma unroll 4
        for (int c = 0; c < 32; ++c) {
            const float mc = __shfl_sync(FULLMASK, mean, c);
            const float vc = __shfl_sync(FULLMASK, var, c);
            const float w0m = s_bw1T[c * 64 + lane];
            const float w1m = s_bw1T[c * 64 + 32 + lane];
            const float w0v = s_bw1T[(c + 32) * 64 + lane];
            const float w1v = s_bw1T[(c + 32) * 64 + 32 + lane];
            const float w0f = s_bw1T[(c + 64) * 64 + lane];
            const float w1f = s_bw1T[(c + 64) * 64 + 32 + lane];
            #pragma unroll
            for (int n = 0; n < NVIEW; ++n) {
                const float fc = __shfl_sync(FULLMASK, fr[n], c);
                a0[n] += w0m * mc + w0v * vc + w0f * fc;
                a1[n] += w1m * mc + w1v * vc + w1f * fc;
            }
        }
        #pragma unroll
        for (int n = 0; n < NVIEW; ++n) { a0[n] = elu_f(a0[n]); a1[n] = elu_f(a1[n]); }

        float xx[NVIEW];
        #pragma unroll
        for (int n = 0; n < NVIEW; ++n) xx[n] = s_bb2[lane];
        #pragma unroll 4
        for (int j = 0; j < 32; ++j) {
            const float wa = s_bw2T[j * 32 + lane];
            const float wb = s_bw2T[(j + 32) * 32 + lane];
            #pragma unroll
            for (int n = 0; n < NVIEW; ++n)
                xx[n] += wa * __shfl_sync(FULLMASK, a0[n], j) + wb * __shfl_sync(FULLMASK, a1[n], j);
        }
        #pragma unroll
        for (int n = 0; n < NVIEW; ++n) xx[n] = elu_f(xx[n]);

        // ---------------- vis MLP: (x*w) 32 -> 32 -> 33 ----------------
        float t[NVIEW];
        #pragma unroll
        for (int n = 0; n < NVIEW; ++n) t[n] = xx[n] * w[n];

        float hv[NVIEW];
        #pragma unroll
        for (int n = 0; n < NVIEW; ++n) hv[n] = s_vb1[lane];
        #pragma unroll 4
        for (int c = 0; c < 32; ++c) {
            const float wv = s_vw1T[c * 32 + lane];
            #pragma unroll
            for (int n = 0; n < NVIEW; ++n)
                hv[n] += wv * __shfl_sync(FULLMASK, t[n], c);
        }
        #pragma unroll
        for (int n = 0; n < NVIEW; ++n) hv[n] = elu_f(hv[n]);

        float ra[NVIEW], va[NVIEW];
        #pragma unroll
        for (int n = 0; n < NVIEW; ++n) { ra[n] = s_vb2[lane]; va[n] = s_vb2[32]; }
        #pragma unroll 4
        for (int h = 0; h < 32; ++h) {
            const float wa = s_vw2T[h * 33 + lane];
            const float wb = s_vw2T[h * 33 + 32];
            #pragma unroll
            for (int n = 0; n < NVIEW; ++n) {
                const float hh = __shfl_sync(FULLMASK, hv[n], h);
                ra[n] += wa * hh;
                va[n] += wb * hh;
            }
        }
        float vs[NVIEW];
        #pragma unroll
        for (int n = 0; n < NVIEW; ++n) {
            xx[n] += elu_f(ra[n]);                       // x = x + x_res
            vs[n]  = sigm_f(elu_f(va[n])) * m[n];        // vis = sigmoid(elu(...)) * mask
        }

        // ---------------- vis2 MLP: (x*vis) 32 -> 32 -> 1 ----------------
        #pragma unroll
        for (int n = 0; n < NVIEW; ++n) t[n] = xx[n] * vs[n];

        float h2[NVIEW];
        #pragma unroll
        for (int n = 0; n < NVIEW; ++n) h2[n] = s_v2b1[lane];
        #pragma unroll 4
        for (int c = 0; c < 32; ++c) {
            const float wv = s_v2w1T[c * 32 + lane];
            #pragma unroll
            for (int n = 0; n < NVIEW; ++n)
                h2[n] += wv * __shfl_sync(FULLMASK, t[n], c);
        }
        #pragma unroll
        for (int n = 0; n < NVIEW; ++n) h2[n] = elu_f(h2[n]);

        float s2[NVIEW];
        #pragma unroll
        for (int n = 0; n < NVIEW; ++n) s2[n] = v2b2;
        #pragma unroll 4
        for (int c = 0; c < 32; ++c) {
            const float wv = s_v2w2[c];
            #pragma unroll
            for (int n = 0; n < NVIEW; ++n)
                s2[n] += wv * __shfl_sync(FULLMASK, h2[n], c);
        }
        float vis2[NVIEW];
        #pragma unroll
        for (int n = 0; n < NVIEW; ++n) vis2[n] = sigm_f(s2[n]) * m[n];

        // ---------------- second weighted mean/var + stat head ----------------
        float vsum = 0.f;
        #pragma unroll
        for (int n = 0; n < NVIEW; ++n) vsum += vis2[n];
        const float vinv = 1.f / (vsum + EPS);
        float w2s = 0.f;
        float w2[NVIEW];
        #pragma unroll
        for (int n = 0; n < NVIEW; ++n) { w2[n] = vis2[n] * vinv; w2s += w2[n]; }

        float mean2 = 0.f;
        #pragma unroll
        for (int n = 0; n < NVIEW; ++n) mean2 += w2[n] * xx[n];
        float var2 = 0.f;
        #pragma unroll
        for (int n = 0; n < NVIEW; ++n) { float d = xx[n] - mean2; var2 += w2[n] * d * d; }
        const float wmean = w2s * 0.125f;   // mean over N=8 views (warp-uniform)

        float o = s_sb[lane];
        const float* swrow = g_sw + lane * 65;
        #pragma unroll 4
        for (int c = 0; c < 32; ++c) {
            o += __ldg(&swrow[c])      * __shfl_sync(FULLMASK, mean2, c);
            o += __ldg(&swrow[32 + c]) * __shfl_sync(FULLMASK, var2, c);
        }
        o += __ldg(&swrow[64]) * wmean;

        out[(b * NF + lane) * G3 + v] = elu_f(o);
    }
}

extern "C" void kernel_launch(void* const* d_in, const int* in_sizes, int n_in,
                              void* d_out, int out_size) {
    (void)in_sizes; (void)n_in; (void)out_size;
    const float* features = (const float*)d_in[0];
    const float* mask     = (const float*)d_in[1];
    const float* depth    = (const float*)d_in[2];
    const float* vdir     = (const float*)d_in[3];
    const float* rde_w1   = (const float*)d_in[4];
    const float* rde_b1   = (const float*)d_in[5];
    const float* rde_w2   = (const float*)d_in[6];
    const float* rde_b2   = (const float*)d_in[7];
    const float* base_w1  = (const float*)d_in[8];
    const float* base_b1  = (const float*)d_in[9];
    const float* base_w2  = (const float*)d_in[10];
    const float* base_b2  = (const float*)d_in[11];
    const float* vis_w1   = (const float*)d_in[12];
    const float* vis_b1   = (const float*)d_in[13];
    const float* vis_w2   = (const float*)d_in[14];
    const float* vis_b2   = (const float*)d_in[15];
    const float* vis2_w1  = (const float*)d_in[16];
    const float* vis2_b1  = (const float*)d_in[17];
    const float* vis2_w2  = (const float*)d_in[18];
    const float* vis2_b2  = (const float*)d_in[19];
    const float* stat_w   = (const float*)d_in[20];
    const float* stat_b   = (const float*)d_in[21];
    float* out = (float*)d_out;

    // 65536 (b,voxel) sites; 8 warps/block * 8 voxels/warp = 64 voxels/block -> 1024 blocks
    ibr_agg_kernel<<<1024, 256>>>(
        features, mask, depth, vdir,
        rde_w1, rde_b1, rde_w2, rde_b2,
        base_w1, base_b1, base_w2, base_b2,
        vis_w1, vis_b1, vis_w2, vis_b2,
        vis2_w1, vis2_b1, vis2_w2, vis2_b2,
        stat_w, stat_b, out);
}

// round 5
// speedup vs baseline: 2.0021x; 2.0021x over previous
#include <cuda_runtime.h>
#include <math.h>

#define G3 32768
#define NVIEW 8

__device__ __forceinline__ float elu_f(float x)  { return x > 0.f ? x : (__expf(x) - 1.f); }
__device__ __forceinline__ float sigm_f(float x) { return 1.f / (1.f + __expf(-x)); }

__global__ __launch_bounds__(128)
void ibr_agg_tpv_kernel(
    const float* __restrict__ features,   // (B,N,32,G3)
    const float* __restrict__ mask,       // (B,N,1,G3)
    const float* __restrict__ depth,      // (B,N,1,G3)
    const float* __restrict__ vdir,       // (B,N,3,G3)
    const float* __restrict__ g_rw1, const float* __restrict__ g_rb1,   // (16,4),(16)
    const float* __restrict__ g_rw2, const float* __restrict__ g_rb2,   // (32,16),(32)
    const float* __restrict__ g_bw1, const float* __restrict__ g_bb1,   // (64,96),(64)
    const float* __restrict__ g_bw2, const float* __restrict__ g_bb2,   // (32,64),(32)
    const float* __restrict__ g_vw1, const float* __restrict__ g_vb1,   // (32,32),(32)
    const float* __restrict__ g_vw2, const float* __restrict__ g_vb2,   // (33,32),(33)
    const float* __restrict__ g_v2w1, const float* __restrict__ g_v2b1, // (32,32),(32)
    const float* __restrict__ g_v2w2, const float* __restrict__ g_v2b2, // (1,32),(1)
    const float* __restrict__ g_sw,  const float* __restrict__ g_sb,    // (32,65),(32)
    float* __restrict__ out)              // (B,32,G3)
{
    // Weights in shared, row-major (out, in) so the in-dim is contiguous for
    // uniform-broadcast LDS.128 (1 load feeds 4 FFMAs). All 16B aligned.
    __shared__ __align__(16) float s_rw1[16 * 4];
    __shared__ __align__(16) float s_rb1[16];
    __shared__ __align__(16) float s_rw2[32 * 16];
    __shared__ __align__(16) float s_rb2[32];
    __shared__ __align__(16) float s_bw1f[64 * 32];   // base_w1 cols 64..95 (feat part)
    __shared__ __align__(16) float s_bw2[32 * 64];
    __shared__ __align__(16) float s_bb2[32];
    __shared__ __align__(16) float s_vw1[32 * 32];
    __shared__ __align__(16) float s_vb1[32];
    __shared__ __align__(16) float s_vw2[33 * 32];
    __shared__ __align__(16) float s_vb2[36];
    __shared__ __align__(16) float s_v2w1[32 * 32];
    __shared__ __align__(16) float s_v2b1[32];
    __shared__ __align__(16) float s_v2w2[32];
    __shared__ __align__(16) float s_sw[32 * 68];     // stat_w rows padded 65->68 for f4 loads
    __shared__ __align__(16) float s_sb[32];

    const int tid = threadIdx.x;

    for (int i = tid; i < 16 * 4;  i += 128) s_rw1[i] = g_rw1[i];
    if (tid < 16) s_rb1[tid] = g_rb1[tid];
    for (int i = tid; i < 32 * 16; i += 128) s_rw2[i] = g_rw2[i];
    if (tid < 32) s_rb2[tid] = g_rb2[tid];
    for (int i = tid; i < 64 * 32; i += 128) { int o = i >> 5, c = i & 31; s_bw1f[i] = g_bw1[o * 96 + 64 + c]; }
    for (int i = tid; i < 32 * 64; i += 128) s_bw2[i] = g_bw2[i];
    if (tid < 32) s_bb2[tid] = g_bb2[tid];
    for (int i = tid; i < 32 * 32; i += 128) s_vw1[i] = g_vw1[i];
    if (tid < 32) s_vb1[tid] = g_vb1[tid];
    for (int i = tid; i < 33 * 32; i += 128) s_vw2[i] = g_vw2[i];
    if (tid < 33) s_vb2[tid] = g_vb2[tid];
    for (int i = tid; i < 32 * 32; i += 128) s_v2w1[i] = g_v2w1[i];
    if (tid < 32) s_v2b1[tid] = g_v2b1[tid];
    if (tid < 32) s_v2w2[tid] = g_v2w2[tid];
    for (int i = tid; i < 32 * 65; i += 128) { int o = i / 65, c = i % 65; s_sw[o * 68 + c] = g_sw[i]; }
    if (tid < 32) s_sb[tid] = g_sb[tid];
    __syncthreads();

    const float EPS  = 1e-8f;
    const float v2b2 = __ldg(g_v2b2);

    const int gv = blockIdx.x * 128 + tid;   // [0, 65536): (b, voxel)
    const int b  = gv >> 15;
    const int v  = gv & (G3 - 1);

    // ---- mask sum ----
    float msum = 0.f;
    #pragma unroll
    for (int n = 0; n < NVIEW; ++n) msum += __ldg(&mask[(b * NVIEW + n) * G3 + v]);
    const float minv = 1.f / (msum + EPS);
    const float ws   = msum * minv;

    // ---- phase 1: per-view rde + feats; accumulate Sum(w f), Sum(w f^2) ----
    float fsave[NVIEW][32];            // per-thread local (coalesced LDL/STL)
    float A1[32], A2[32];
    #pragma unroll
    for (int c = 0; c < 32; ++c) { A1[c] = 0.f; A2[c] = 0.f; }

    #pragma unroll 1
    for (int n = 0; n < NVIEW; ++n) {
        const int bn = b * NVIEW + n;
        const float i0 = __ldg(&vdir[(bn * 3 + 0) * G3 + v]);
        const float i1 = __ldg(&vdir[(bn * 3 + 1) * G3 + v]);
        const float i2 = __ldg(&vdir[(bn * 3 + 2) * G3 + v]);
        const float i3 = __ldg(&depth[bn * G3 + v]);
        const float wn = __ldg(&mask[bn * G3 + v]) * minv;

        float h16[16];
        #pragma unroll
        for (int o = 0; o < 16; ++o) {
            const float4 w = *reinterpret_cast<const float4*>(&s_rw1[o * 4]);
            h16[o] = elu_f(s_rb1[o] + w.x * i0 + w.y * i1 + w.z * i2 + w.w * i3);
        }

        const float* fbase = &features[(bn * 32) * G3 + v];
        #pragma unroll
        for (int c = 0; c < 32; ++c) {
            float acc = s_rb2[c];
            #pragma unroll
            for (int o = 0; o < 16; o += 4) {
                const float4 w = *reinterpret_cast<const float4*>(&s_rw2[c * 16 + o]);
                acc += w.x * h16[o] + w.y * h16[o + 1] + w.z * h16[o + 2] + w.w * h16[o + 3];
            }
            const float f = __ldg(&fbase[c * G3]) + elu_f(acc);
            fsave[n][c] = f;
            A1[c] += wn * f;
            A2[c] += wn * f * f;
        }
    }

    // mean / var  (var = Sum w f^2 - mean^2 (2 - ws))
    float mean[32], var[32];
    #pragma unroll
    for (int c = 0; c < 32; ++c) {
        mean[c] = A1[c];
        var[c]  = A2[c] - mean[c] * mean[c] * (2.f - ws);
    }

    // ---- hbase[o] = bb1[o] + bw1[o,0:32].mean + bw1[o,32:64].var (per voxel) ----
    float hbase[64];                   // per-thread local (dynamic-indexed below)
    #pragma unroll 1
    for (int o = 0; o < 64; ++o) {
        float acc = __ldg(&g_bb1[o]);
        const float4* wr = reinterpret_cast<const float4*>(&g_bw1[o * 96]);
        #pragma unroll
        for (int c = 0; c < 32; c += 4) {
            const float4 wm = __ldg(&wr[c / 4]);
            const float4 wv = __ldg(&wr[8 + c / 4]);
            acc += wm.x * mean[c] + wm.y * mean[c + 1] + wm.z * mean[c + 2] + wm.w * mean[c + 3];
            acc += wv.x * var[c]  + wv.y * var[c + 1]  + wv.z * var[c + 2]  + wv.w * var[c + 3];
        }
        hbase[o] = acc;
    }

    // ---- phase 2: per-view MLP stack; accumulate S, U=Sum(vis2 x), V=Sum(vis2 x^2) ----
    float U[32], Vv[32];
    float S = 0.f;
    #pragma unroll
    for (int c = 0; c < 32; ++c) { U[c] = 0.f; Vv[c] = 0.f; }

    #pragma unroll 1
    for (int n = 0; n < NVIEW; ++n) {
        const int bn = b * NVIEW + n;
        const float mval = __ldg(&mask[bn * G3 + v]);
        const float wn   = mval * minv;

        float f[32];
        #pragma unroll
        for (int c = 0; c < 32; ++c) f[c] = fsave[n][c];

        // base: h = elu(hbase + bw1f.f) (64), xx = elu(bb2 + bw2.elu(h)) (32), fused by 8-chunks
        float xx[32];
        #pragma unroll
        for (int j = 0; j < 32; ++j) xx[j] = s_bb2[j];

        #pragma unroll 1
        for (int oc = 0; oc < 8; ++oc) {
            const int o8 = oc * 8;
            float h[8];
            #pragma unroll
            for (int k = 0; k < 8; ++k) {
                float acc = hbase[o8 + k];
                const float* wr = &s_bw1f[(o8 + k) * 32];
                #pragma unroll
                for (int c = 0; c < 32; c += 4) {
                    const float4 w = *reinterpret_cast<const float4*>(&wr[c]);
                    acc += w.x * f[c] + w.y * f[c + 1] + w.z * f[c + 2] + w.w * f[c + 3];
                }
                h[k] = elu_f(acc);
            }
            #pragma unroll
            for (int j = 0; j < 32; ++j) {
                const float* wr = &s_bw2[j * 64 + o8];
                const float4 wa = *reinterpret_cast<const float4*>(&wr[0]);
                const float4 wb = *reinterpret_cast<const float4*>(&wr[4]);
                xx[j] += wa.x * h[0] + wa.y * h[1] + wa.z * h[2] + wa.w * h[3]
                       + wb.x * h[4] + wb.y * h[5] + wb.z * h[6] + wb.w * h[7];
            }
        }
        #pragma unroll
        for (int j = 0; j < 32; ++j) xx[j] = elu_f(xx[j]);

        // vis: t = xx*w; hv = elu(vw1.t); xv = vb2 + vw2.hv (33)
        float t[32];
        #pragma unroll
        for (int c = 0; c < 32; ++c) t[c] = xx[c] * wn;

        float ra[32];
        float va = s_vb2[32];
        #pragma unroll
        for (int j = 0; j < 32; ++j) ra[j] = s_vb2[j];

        #pragma unroll 1
        for (int oc = 0; oc < 4; ++oc) {
            const int o8 = oc * 8;
            float h[8];
            #pragma unroll
            for (int k = 0; k < 8; ++k) {
                float acc = s_vb1[o8 + k];
                const float* wr = &s_vw1[(o8 + k) * 32];
                #pragma unroll
                for (int c = 0; c < 32; c += 4) {
                    const float4 w = *reinterpret_cast<const float4*>(&wr[c]);
                    acc += w.x * t[c] + w.y * t[c + 1] + w.z * t[c + 2] + w.w * t[c + 3];
                }
                h[k] = elu_f(acc);
            }
            #pragma unroll
            for (int j = 0; j < 32; ++j) {
                const float* wr = &s_vw2[j * 32 + o8];
                const float4 wa = *reinterpret_cast<const float4*>(&wr[0]);
                const float4 wb = *reinterpret_cast<const float4*>(&wr[4]);
                ra[j] += wa.x * h[0] + wa.y * h[1] + wa.z * h[2] + wa.w * h[3]
                       + wb.x * h[4] + wb.y * h[5] + wb.z * h[6] + wb.w * h[7];
            }
            {
                const float* wr = &s_vw2[32 * 32 + o8];
                const float4 wa = *reinterpret_cast<const float4*>(&wr[0]);
                const float4 wb = *reinterpret_cast<const float4*>(&wr[4]);
                va += wa.x * h[0] + wa.y * h[1] + wa.z * h[2] + wa.w * h[3]
                    + wb.x * h[4] + wb.y * h[5] + wb.z * h[6] + wb.w * h[7];
            }
        }
        #pragma unroll
        for (int j = 0; j < 32; ++j) xx[j] += elu_f(ra[j]);     // x = x + x_res
        const float vis = sigm_f(elu_f(va)) * mval;

        // vis2: t2 = xx*vis; s2 = v2b2 + v2w2.elu(v2w1.t2)
        #pragma unroll
        for (int c = 0; c < 32; ++c) t[c] = xx[c] * vis;

        float s2 = v2b2;
        #pragma unroll 1
        for (int oc = 0; oc < 4; ++oc) {
            const int o8 = oc * 8;
            #pragma unroll
            for (int k = 0; k < 8; ++k) {
                float acc = s_v2b1[o8 + k];
                const float* wr = &s_v2w1[(o8 + k) * 32];
                #pragma unroll
                for (int c = 0; c < 32; c += 4) {
                    const float4 w = *reinterpret_cast<const float4*>(&wr[c]);
                    acc += w.x * t[c] + w.y * t[c + 1] + w.z * t[c + 2] + w.w * t[c + 3];
                }
                s2 += s_v2w2[o8 + k] * elu_f(acc);
            }
        }
        const float vis2 = sigm_f(s2) * mval;

        S += vis2;
        #pragma unroll
        for (int c = 0; c < 32; ++c) {
            U[c]  += vis2 * xx[c];
            Vv[c] += vis2 * xx[c] * xx[c];
        }
    }

    // ---- second mean/var + stat head ----
    const float Sinv  = 1.f / (S + EPS);
    const float w2s   = S * Sinv;
    const float wmean = w2s * 0.125f;

    float mean2[32], var2[32];
    #pragma unroll
    for (int c = 0; c < 32; ++c) {
        mean2[c] = U[c] * Sinv;
        var2[c]  = Vv[c] * Sinv - mean2[c] * mean2[c] * (2.f - w2s);
    }

    #pragma unroll 1
    for (int o = 0; o < 32; ++o) {
        float acc = s_sb[o];
        const float* wr = &s_sw[o * 68];
        #pragma unroll
        for (int c = 0; c < 32; c += 4) {
            const float4 wm = *reinterpret_cast<const float4*>(&wr[c]);
            const float4 wv = *reinterpret_cast<const float4*>(&wr[32 + c]);
            acc += wm.x * mean2[c] + wm.y * mean2[c + 1] + wm.z * mean2[c + 2] + wm.w * mean2[c + 3];
            acc += wv.x * var2[c]  + wv.y * var2[c + 1]  + wv.z * var2[c + 2]  + wv.w * var2[c + 3];
        }
        acc += wr[64] * wmean;
        out[(b * 32 + o) * G3 + v] = elu_f(acc);
    }
}

extern "C" void kernel_launch(void* const* d_in, const int* in_sizes, int n_in,
                              void* d_out, int out_size) {
    (void)in_sizes; (void)n_in; (void)out_size;
    const float* features = (const float*)d_in[0];
    const float* mask     = (const float*)d_in[1];
    const float* depth    = (const float*)d_in[2];
    const float* vdir     = (const float*)d_in[3];
    const float* rde_w1   = (const float*)d_in[4];
    const float* rde_b1   = (const float*)d_in[5];
    const float* rde_w2   = (const float*)d_in[6];
    const float* rde_b2   = (const float*)d_in[7];
    const float* base_w1  = (const float*)d_in[8];
    const float* base_b1  = (const float*)d_in[9];
    const float* base_w2  = (const float*)d_in[10];
    const float* base_b2  = (const float*)d_in[11];
    const float* vis_w1   = (const float*)d_in[12];
    const float* vis_b1   = (const float*)d_in[13];
    const float* vis_w2   = (const float*)d_in[14];
    const float* vis_b2   = (const float*)d_in[15];
    const float* vis2_w1  = (const float*)d_in[16];
    const float* vis2_b1  = (const float*)d_in[17];
    const float* vis2_w2  = (const float*)d_in[18];
    const float* vis2_b2  = (const float*)d_in[19];
    const float* stat_w   = (const float*)d_in[20];
    const float* stat_b   = (const float*)d_in[21];
    float* out = (float*)d_out;

    // 65536 (b,voxel) sites, thread-per-voxel: 512 blocks x 128 threads
    ibr_agg_tpv_kernel<<<512, 128>>>(
        features, mask, depth, vdir,
        rde_w1, rde_b1, rde_w2, rde_b2,
        base_w1, base_b1, base_w2, base_b2,
        vis_w1, vis_b1, vis_w2, vis_b2,
        vis2_w1, vis2_b1, vis2_w2, vis2_b2,
        stat_w, stat_b, out);
}